// round 3
// baseline (speedup 1.0000x reference)
#include <cuda_runtime.h>
#include <math.h>

#define NNODES 50000
#define NEDGES 800000
#define ETOT   (NEDGES + NNODES)
#define HC     128
#define NOUTC  40
#define NEG_SLOPE 0.2f
#define BN_EPS 1e-5f

// ---------------- scratch (static device arrays; no runtime alloc) ----------
static __device__ __align__(16) float g_h[NNODES * HC];
static __device__ __align__(16) float g_x1[NNODES * HC];
static __device__ __align__(16) float g_x2[NNODES * HC];
static __device__ float g_asrc[NNODES * 2];
static __device__ float g_adst[NNODES * 2];
static __device__ __align__(16) float g_e[ETOT * 2];     // e, then ex (CSR order)
static __device__ float g_invden[NNODES * 2];
static __device__ int   g_deg[NNODES];
static __device__ int   g_fill[NNODES];
static __device__ int   g_rowptr[NNODES + 1];
static __device__ int   g_csr_src[ETOT];
static __device__ __align__(16) float g_logits[NNODES * NOUTC];
static __device__ int   g_is64;

// ---------------- edge index dtype detection --------------------------------
__global__ void k_detect(const int* ei32) {
    if (threadIdx.x == 0 && blockIdx.x == 0) {
        int any = 0;
        #pragma unroll 1
        for (int i = 0; i < 256; i++) any |= ei32[2 * i + 1];
        g_is64 = (any == 0) ? 1 : 0;   // int64 node ids < 50000 -> high words all 0
    }
}

__device__ __forceinline__ int edge_idx(const void* ei, int pos) {
    if (g_is64) return (int)((const long long*)ei)[pos];
    return ((const int*)ei)[pos];
}

// ---------------- CSR build --------------------------------------------------
__global__ void k_zero() {
    int i = blockIdx.x * blockDim.x + threadIdx.x;
    if (i < NNODES) { g_deg[i] = 0; g_fill[i] = 0; }
}

__global__ void k_count(const void* ei) {
    int i = blockIdx.x * blockDim.x + threadIdx.x;
    if (i >= ETOT) return;
    int d = (i < NEDGES) ? edge_idx(ei, NEDGES + i) : (i - NEDGES);
    atomicAdd(&g_deg[d], 1);
}

__global__ void k_scan() {
    __shared__ int s[1024];
    int t = threadIdx.x;
    if (t == 0) g_rowptr[0] = 0;
    int carry = 0;
    for (int base = 0; base < NNODES; base += 1024) {
        int idx = base + t;
        int v = (idx < NNODES) ? g_deg[idx] : 0;
        s[t] = v;
        __syncthreads();
        for (int o = 1; o < 1024; o <<= 1) {
            int add = (t >= o) ? s[t - o] : 0;
            __syncthreads();
            s[t] += add;
            __syncthreads();
        }
        if (idx < NNODES) g_rowptr[idx + 1] = s[t] + carry;
        carry += s[1023];
        __syncthreads();
    }
}

__global__ void k_fill(const void* ei) {
    int i = blockIdx.x * blockDim.x + threadIdx.x;
    if (i >= ETOT) return;
    int s, d;
    if (i < NEDGES) { s = edge_idx(ei, i); d = edge_idx(ei, NEDGES + i); }
    else            { s = d = i - NEDGES; }
    int pos = g_rowptr[d] + atomicAdd(&g_fill[d], 1);
    g_csr_src[pos] = s;
}

// ---------------- SGEMM (A[M,K] * B[K,Nc]) -----------------------------------
#define BM 64
#define BN 64
#define BK 16
__global__ void k_sgemm(const float* __restrict__ A, const float* __restrict__ B,
                        float* __restrict__ C, int M, int Nc, int K) {
    __shared__ __align__(16) float As[BK][BM];   // transposed A tile
    __shared__ __align__(16) float Bs[BK][BN];
    int t  = threadIdx.x;
    int tx = t & 15, ty = t >> 4;
    int rowBase = blockIdx.y * BM;
    int colBase = blockIdx.x * BN;

    float acc[4][4] = {};
    int aRow = t >> 2;           // 0..63
    int aK4  = (t & 3) * 4;      // 0,4,8,12
    int bK   = t >> 4;           // 0..15
    int bC4  = (t & 15) * 4;     // 0..60

    for (int k0 = 0; k0 < K; k0 += BK) {
        float4 av = make_float4(0.f, 0.f, 0.f, 0.f);
        int gr = rowBase + aRow;
        if (gr < M) av = *reinterpret_cast<const float4*>(A + (size_t)gr * K + k0 + aK4);
        As[aK4 + 0][aRow] = av.x; As[aK4 + 1][aRow] = av.y;
        As[aK4 + 2][aRow] = av.z; As[aK4 + 3][aRow] = av.w;

        float4 bv = make_float4(0.f, 0.f, 0.f, 0.f);
        int gc = colBase + bC4;
        const float* brow = B + (size_t)(k0 + bK) * Nc;
        if (gc + 3 < Nc) bv = *reinterpret_cast<const float4*>(brow + gc);
        else {
            if (gc + 0 < Nc) bv.x = brow[gc + 0];
            if (gc + 1 < Nc) bv.y = brow[gc + 1];
            if (gc + 2 < Nc) bv.z = brow[gc + 2];
            if (gc + 3 < Nc) bv.w = brow[gc + 3];
        }
        *reinterpret_cast<float4*>(&Bs[bK][bC4]) = bv;
        __syncthreads();

        #pragma unroll
        for (int k = 0; k < BK; k++) {
            float4 a4 = *reinterpret_cast<const float4*>(&As[k][ty * 4]);
            float4 b4 = *reinterpret_cast<const float4*>(&Bs[k][tx * 4]);
            float a[4] = {a4.x, a4.y, a4.z, a4.w};
            float b[4] = {b4.x, b4.y, b4.z, b4.w};
            #pragma unroll
            for (int i = 0; i < 4; i++)
                #pragma unroll
                for (int j = 0; j < 4; j++)
                    acc[i][j] += a[i] * b[j];
        }
        __syncthreads();
    }

    #pragma unroll
    for (int i = 0; i < 4; i++) {
        int gr = rowBase + ty * 4 + i;
        if (gr >= M) continue;
        #pragma unroll
        for (int j = 0; j < 4; j++) {
            int gc = colBase + tx * 4 + j;
            if (gc < Nc) C[(size_t)gr * Nc + gc] = acc[i][j];
        }
    }
}

// ---------------- per-node attention coefficients ----------------------------
__global__ void k_attn(const float* __restrict__ att_src, const float* __restrict__ att_dst) {
    int gt = blockIdx.x * blockDim.x + threadIdx.x;
    int w = gt >> 5, lane = gt & 31;
    if (w >= NNODES) return;
    float4 hv = *reinterpret_cast<const float4*>(g_h + (size_t)w * HC + lane * 4);
    float4 as = *reinterpret_cast<const float4*>(att_src + lane * 4);
    float4 ad = *reinterpret_cast<const float4*>(att_dst + lane * 4);
    float ss = hv.x * as.x + hv.y * as.y + hv.z * as.z + hv.w * as.w;
    float sd = hv.x * ad.x + hv.y * ad.y + hv.z * ad.z + hv.w * ad.w;
    for (int o = 8; o; o >>= 1) {            // reduce within 16-lane head group
        ss += __shfl_xor_sync(0xffffffffu, ss, o);
        sd += __shfl_xor_sync(0xffffffffu, sd, o);
    }
    if ((lane & 15) == 0) {
        int h = lane >> 4;
        g_asrc[w * 2 + h] = ss;
        g_adst[w * 2 + h] = sd;
    }
}

// ---------------- per-node segment softmax (gather, no atomics) --------------
__global__ void k_softmax() {
    int gt = blockIdx.x * blockDim.x + threadIdx.x;
    int w = gt >> 5, lane = gt & 31;
    if (w >= NNODES) return;
    int beg = g_rowptr[w], end = g_rowptr[w + 1];
    float ad0 = g_adst[w * 2], ad1 = g_adst[w * 2 + 1];
    float m0 = -3.0e38f, m1 = -3.0e38f;
    for (int p = beg + lane; p < end; p += 32) {
        int s = g_csr_src[p];
        float e0 = g_asrc[s * 2]     + ad0;
        float e1 = g_asrc[s * 2 + 1] + ad1;
        e0 = e0 > 0.f ? e0 : NEG_SLOPE * e0;
        e1 = e1 > 0.f ? e1 : NEG_SLOPE * e1;
        float2 ev; ev.x = e0; ev.y = e1;
        *reinterpret_cast<float2*>(g_e + 2 * p) = ev;
        m0 = fmaxf(m0, e0); m1 = fmaxf(m1, e1);
    }
    for (int o = 16; o; o >>= 1) {
        m0 = fmaxf(m0, __shfl_xor_sync(0xffffffffu, m0, o));
        m1 = fmaxf(m1, __shfl_xor_sync(0xffffffffu, m1, o));
    }
    float s0 = 0.f, s1 = 0.f;
    for (int p = beg + lane; p < end; p += 32) {
        float2 ev = *reinterpret_cast<float2*>(g_e + 2 * p);
        float ex0 = expf(ev.x - m0);
        float ex1 = expf(ev.y - m1);
        ev.x = ex0; ev.y = ex1;
        *reinterpret_cast<float2*>(g_e + 2 * p) = ev;
        s0 += ex0; s1 += ex1;
    }
    for (int o = 16; o; o >>= 1) {
        s0 += __shfl_xor_sync(0xffffffffu, s0, o);
        s1 += __shfl_xor_sync(0xffffffffu, s1, o);
    }
    if (lane == 0) {
        g_invden[w * 2]     = 1.f / (s0 + 1e-16f);
        g_invden[w * 2 + 1] = 1.f / (s1 + 1e-16f);
    }
}

// ---------------- weighted aggregate (gather) + fused epilogue ---------------
template <bool FIRST>
__global__ void k_agg(const float* __restrict__ bias,
                      const float* __restrict__ gamma, const float* __restrict__ beta,
                      const float* __restrict__ mean,  const float* __restrict__ var) {
    int gt = blockIdx.x * blockDim.x + threadIdx.x;
    int w = gt >> 5, lane = gt & 31;
    if (w >= NNODES) return;
    int beg = g_rowptr[w], end = g_rowptr[w + 1];
    float invh = (lane < 16) ? g_invden[w * 2] : g_invden[w * 2 + 1];
    float4 acc = make_float4(0.f, 0.f, 0.f, 0.f);
    for (int p = beg; p < end; p++) {
        int s = g_csr_src[p];                                   // broadcast
        float2 ev = *reinterpret_cast<const float2*>(g_e + 2 * p);
        float alpha = ((lane < 16) ? ev.x : ev.y) * invh;
        float4 v = *reinterpret_cast<const float4*>(g_h + (size_t)s * HC + lane * 4);
        acc.x += alpha * v.x; acc.y += alpha * v.y;
        acc.z += alpha * v.z; acc.w += alpha * v.w;
    }
    int j = lane * 4;
    float4 b = *reinterpret_cast<const float4*>(bias + j);
    float4 r = make_float4(acc.x + b.x, acc.y + b.y, acc.z + b.z, acc.w + b.w);
    if (FIRST) {
        float4 gm = *reinterpret_cast<const float4*>(gamma + j);
        float4 bt = *reinterpret_cast<const float4*>(beta + j);
        float4 mn = *reinterpret_cast<const float4*>(mean + j);
        float4 vr = *reinterpret_cast<const float4*>(var + j);
        r.x = (r.x - mn.x) * rsqrtf(vr.x + BN_EPS) * gm.x + bt.x;
        r.y = (r.y - mn.y) * rsqrtf(vr.y + BN_EPS) * gm.y + bt.y;
        r.z = (r.z - mn.z) * rsqrtf(vr.z + BN_EPS) * gm.z + bt.z;
        r.w = (r.w - mn.w) * rsqrtf(vr.w + BN_EPS) * gm.w + bt.w;
        r.x = r.x > 0.f ? r.x : expm1f(r.x);
        r.y = r.y > 0.f ? r.y : expm1f(r.y);
        r.z = r.z > 0.f ? r.z : expm1f(r.z);
        r.w = r.w > 0.f ? r.w : expm1f(r.w);
        *reinterpret_cast<float4*>(g_x1 + (size_t)w * HC + j) = r;
    } else {
        float4 p1 = *reinterpret_cast<const float4*>(g_x1 + (size_t)w * HC + j);
        r.x = fmaxf(r.x, p1.x); r.y = fmaxf(r.y, p1.y);
        r.z = fmaxf(r.z, p1.z); r.w = fmaxf(r.w, p1.w);        // JK 'max' fused
        *reinterpret_cast<float4*>(g_x2 + (size_t)w * HC + j) = r;
    }
}

// ---------------- bias + row log-softmax -------------------------------------
__global__ void k_lsm(const float* __restrict__ bf, float* __restrict__ out) {
    int gt = blockIdx.x * blockDim.x + threadIdx.x;
    int w = gt >> 5, lane = gt & 31;
    if (w >= NNODES) return;
    const float* row = g_logits + (size_t)w * NOUTC;
    float l0 = row[lane] + bf[lane];                            // lanes 0..31
    float l1 = (lane < 8) ? (row[32 + lane] + bf[32 + lane]) : -3.0e38f;
    float m = fmaxf(l0, l1);
    for (int o = 16; o; o >>= 1) m = fmaxf(m, __shfl_xor_sync(0xffffffffu, m, o));
    float s = expf(l0 - m) + ((lane < 8) ? expf(l1 - m) : 0.f);
    for (int o = 16; o; o >>= 1) s += __shfl_xor_sync(0xffffffffu, s, o);
    float lse = m + logf(s);
    out[(size_t)w * NOUTC + lane] = l0 - lse;
    if (lane < 8) out[(size_t)w * NOUTC + 32 + lane] = l1 - lse;
}

// ---------------- launch -----------------------------------------------------
extern "C" void kernel_launch(void* const* d_in, const int* in_sizes, int n_in,
                              void* d_out, int out_size) {
    const float* x     = (const float*)d_in[0];
    const void*  ei    = d_in[1];
    const float* W1    = (const float*)d_in[2];
    const float* as1   = (const float*)d_in[3];
    const float* ad1   = (const float*)d_in[4];
    const float* b1    = (const float*)d_in[5];
    const float* gamma = (const float*)d_in[6];
    const float* beta  = (const float*)d_in[7];
    const float* mean  = (const float*)d_in[8];
    const float* var   = (const float*)d_in[9];
    const float* W2    = (const float*)d_in[10];
    const float* as2   = (const float*)d_in[11];
    const float* ad2   = (const float*)d_in[12];
    const float* b2    = (const float*)d_in[13];
    const float* Wf    = (const float*)d_in[14];
    const float* bf    = (const float*)d_in[15];
    float* out = (float*)d_out;

    float *hP, *x1P, *x2P, *lgP;
    cudaGetSymbolAddress((void**)&hP,  g_h);
    cudaGetSymbolAddress((void**)&x1P, g_x1);
    cudaGetSymbolAddress((void**)&x2P, g_x2);
    cudaGetSymbolAddress((void**)&lgP, g_logits);

    const int WPN = (NNODES * 32 + 255) / 256;   // warp-per-node grids

    k_detect<<<1, 32>>>((const int*)ei);
    k_zero<<<(NNODES + 255) / 256, 256>>>();
    k_count<<<(ETOT + 255) / 256, 256>>>(ei);
    k_scan<<<1, 1024>>>();
    k_fill<<<(ETOT + 255) / 256, 256>>>(ei);

    dim3 g128((HC + BN - 1) / BN, (NNODES + BM - 1) / BM);
    dim3 g40((NOUTC + BN - 1) / BN, (NNODES + BM - 1) / BM);

    // layer 1
    k_sgemm<<<g128, 256>>>(x, W1, hP, NNODES, HC, HC);
    k_attn<<<WPN, 256>>>(as1, ad1);
    k_softmax<<<WPN, 256>>>();
    k_agg<true><<<WPN, 256>>>(b1, gamma, beta, mean, var);

    // layer 2
    k_sgemm<<<g128, 256>>>(x1P, W2, hP, NNODES, HC, HC);
    k_attn<<<WPN, 256>>>(as2, ad2);
    k_softmax<<<WPN, 256>>>();
    k_agg<false><<<WPN, 256>>>(b2, nullptr, nullptr, nullptr, nullptr);

    // head
    k_sgemm<<<g40, 256>>>(x2P, Wf, lgP, NNODES, NOUTC, HC);
    k_lsm<<<WPN, 256>>>(bf, out);
}

// round 4
// speedup vs baseline: 1.1478x; 1.1478x over previous
#include <cuda_runtime.h>
#include <math.h>

#define NNODES 50000
#define NEDGES 800000
#define ETOT   (NEDGES + NNODES)
#define HC     128
#define NOUTC  40
#define NEG_SLOPE 0.2f
#define BN_EPS 1e-5f
#define NSCANB ((NNODES + 1023) / 1024)

// ---------------- scratch (static device arrays; no runtime alloc) ----------
static __device__ __align__(16) float g_h[NNODES * HC];
static __device__ __align__(16) float g_x1[NNODES * HC];
static __device__ __align__(16) float g_x2[NNODES * HC];
static __device__ float g_asrc[NNODES * 2];
static __device__ float g_adst[NNODES * 2];
static __device__ __align__(16) float g_e[ETOT * 2];     // e, then ex (CSR order)
static __device__ float g_invden[NNODES * 2];
static __device__ int   g_deg[NNODES];
static __device__ int   g_fill[NNODES];
static __device__ int   g_rowptr[NNODES + 1];
static __device__ int   g_bsum[NSCANB + 1];
static __device__ int   g_csr_src[ETOT];
static __device__ __align__(16) float g_logits[NNODES * NOUTC];
static __device__ int   g_is64;

// ---------------- edge index dtype detection --------------------------------
__global__ void k_detect(const int* ei32) {
    if (threadIdx.x == 0 && blockIdx.x == 0) {
        int any = 0;
        #pragma unroll 1
        for (int i = 0; i < 256; i++) any |= ei32[2 * i + 1];
        g_is64 = (any == 0) ? 1 : 0;   // int64 node ids < 50000 -> high words all 0
    }
}

__device__ __forceinline__ int edge_idx(const void* ei, int pos) {
    if (g_is64) return (int)((const long long*)ei)[pos];
    return ((const int*)ei)[pos];
}

// ---------------- CSR build --------------------------------------------------
__global__ void k_zero() {
    int i = blockIdx.x * blockDim.x + threadIdx.x;
    if (i < NNODES) { g_deg[i] = 0; g_fill[i] = 0; }
}

__global__ void k_count(const void* ei) {
    int i = blockIdx.x * blockDim.x + threadIdx.x;
    if (i >= ETOT) return;
    int d = (i < NEDGES) ? edge_idx(ei, NEDGES + i) : (i - NEDGES);
    atomicAdd(&g_deg[d], 1);
}

// 3-phase parallel scan: block scans -> block-sum scan -> offset add
__global__ void k_scan1() {
    __shared__ int s[1024];
    int t = threadIdx.x;
    int idx = blockIdx.x * 1024 + t;
    int v = (idx < NNODES) ? g_deg[idx] : 0;
    s[t] = v;
    __syncthreads();
    #pragma unroll
    for (int o = 1; o < 1024; o <<= 1) {
        int add = (t >= o) ? s[t - o] : 0;
        __syncthreads();
        s[t] += add;
        __syncthreads();
    }
    if (idx < NNODES) g_rowptr[idx + 1] = s[t];
    if (t == 1023) g_bsum[blockIdx.x] = s[1023];
    if (idx == 0) g_rowptr[0] = 0;
}

__global__ void k_scan2() {
    if (threadIdx.x == 0) {
        int acc = 0;
        #pragma unroll 1
        for (int i = 0; i < NSCANB; i++) { int v = g_bsum[i]; g_bsum[i] = acc; acc += v; }
    }
}

__global__ void k_scan3() {
    int idx = blockIdx.x * blockDim.x + threadIdx.x;
    if (idx < NNODES) g_rowptr[idx + 1] += g_bsum[idx >> 10];
}

__global__ void k_fill(const void* ei) {
    int i = blockIdx.x * blockDim.x + threadIdx.x;
    if (i >= ETOT) return;
    int s, d;
    if (i < NEDGES) { s = edge_idx(ei, i); d = edge_idx(ei, NEDGES + i); }
    else            { s = d = i - NEDGES; }
    int pos = g_rowptr[d] + atomicAdd(&g_fill[d], 1);
    g_csr_src[pos] = s;
}

// ---------------- packed-f32x2 SGEMM, specialized K=Nc=128 -------------------
// 128x128x16 tile, 256 threads, 8x8 microtile with f32x2 (FFMA2) accumulators.
__device__ __forceinline__ unsigned long long pack2(float a) {
    unsigned long long r;
    unsigned int u = __float_as_uint(a);
    asm("mov.b64 %0, {%1, %1};" : "=l"(r) : "r"(u));
    return r;
}

__global__ __launch_bounds__(256, 2)
void k_sgemm128(const float* __restrict__ A, const float* __restrict__ B,
                float* __restrict__ C, int M) {
    __shared__ __align__(16) float As[16][128];   // transposed A tile
    __shared__ __align__(16) float Bs[16][128];
    int t  = threadIdx.x;
    int tx = t & 15, ty = t >> 4;
    int rowBase = blockIdx.x * 128;

    unsigned long long acc[8][4];
    #pragma unroll
    for (int i = 0; i < 8; i++)
        #pragma unroll
        for (int j = 0; j < 4; j++) acc[i][j] = 0ull;

    int aRow = t >> 1;          // 0..127
    int aK   = (t & 1) * 8;     // 0 or 8
    int bRow = t >> 4;          // 0..15
    int bC   = (t & 15) * 8;    // 0..120

    for (int k0 = 0; k0 < 128; k0 += 16) {
        float4 av0 = make_float4(0.f, 0.f, 0.f, 0.f), av1 = av0;
        int gr = rowBase + aRow;
        if (gr < M) {
            const float* ap = A + (size_t)gr * 128 + k0 + aK;
            av0 = *reinterpret_cast<const float4*>(ap);
            av1 = *reinterpret_cast<const float4*>(ap + 4);
        }
        As[aK + 0][aRow] = av0.x; As[aK + 1][aRow] = av0.y;
        As[aK + 2][aRow] = av0.z; As[aK + 3][aRow] = av0.w;
        As[aK + 4][aRow] = av1.x; As[aK + 5][aRow] = av1.y;
        As[aK + 6][aRow] = av1.z; As[aK + 7][aRow] = av1.w;

        const float* bp = B + (size_t)(k0 + bRow) * 128 + bC;
        *reinterpret_cast<float4*>(&Bs[bRow][bC])     = *reinterpret_cast<const float4*>(bp);
        *reinterpret_cast<float4*>(&Bs[bRow][bC + 4]) = *reinterpret_cast<const float4*>(bp + 4);
        __syncthreads();

        #pragma unroll
        for (int k = 0; k < 16; k++) {
            float4 a0 = *reinterpret_cast<const float4*>(&As[k][ty * 8]);
            float4 a1 = *reinterpret_cast<const float4*>(&As[k][ty * 8 + 4]);
            unsigned long long aa[8];
            aa[0] = pack2(a0.x); aa[1] = pack2(a0.y); aa[2] = pack2(a0.z); aa[3] = pack2(a0.w);
            aa[4] = pack2(a1.x); aa[5] = pack2(a1.y); aa[6] = pack2(a1.z); aa[7] = pack2(a1.w);
            const unsigned long long* bpp =
                reinterpret_cast<const unsigned long long*>(&Bs[k][tx * 8]);
            unsigned long long b0 = bpp[0], b1 = bpp[1], b2 = bpp[2], b3 = bpp[3];
            #pragma unroll
            for (int i = 0; i < 8; i++) {
                asm("fma.rn.f32x2 %0, %1, %2, %0;" : "+l"(acc[i][0]) : "l"(aa[i]), "l"(b0));
                asm("fma.rn.f32x2 %0, %1, %2, %0;" : "+l"(acc[i][1]) : "l"(aa[i]), "l"(b1));
                asm("fma.rn.f32x2 %0, %1, %2, %0;" : "+l"(acc[i][2]) : "l"(aa[i]), "l"(b2));
                asm("fma.rn.f32x2 %0, %1, %2, %0;" : "+l"(acc[i][3]) : "l"(aa[i]), "l"(b3));
            }
        }
        __syncthreads();
    }

    #pragma unroll
    for (int i = 0; i < 8; i++) {
        int gr = rowBase + ty * 8 + i;
        if (gr >= M) continue;
        unsigned long long* crow =
            reinterpret_cast<unsigned long long*>(C + (size_t)gr * 128 + tx * 8);
        crow[0] = acc[i][0]; crow[1] = acc[i][1];
        crow[2] = acc[i][2]; crow[3] = acc[i][3];
    }
}

// ---------------- generic SGEMM (used for the 40-col head) -------------------
#define BM 64
#define BN 64
#define BK 16
__global__ void k_sgemm(const float* __restrict__ A, const float* __restrict__ B,
                        float* __restrict__ C, int M, int Nc, int K) {
    __shared__ __align__(16) float As[BK][BM];   // transposed A tile
    __shared__ __align__(16) float Bs[BK][BN];
    int t  = threadIdx.x;
    int tx = t & 15, ty = t >> 4;
    int rowBase = blockIdx.y * BM;
    int colBase = blockIdx.x * BN;

    float acc[4][4] = {};
    int aRow = t >> 2;
    int aK4  = (t & 3) * 4;
    int bK   = t >> 4;
    int bC4  = (t & 15) * 4;

    for (int k0 = 0; k0 < K; k0 += BK) {
        float4 av = make_float4(0.f, 0.f, 0.f, 0.f);
        int gr = rowBase + aRow;
        if (gr < M) av = *reinterpret_cast<const float4*>(A + (size_t)gr * K + k0 + aK4);
        As[aK4 + 0][aRow] = av.x; As[aK4 + 1][aRow] = av.y;
        As[aK4 + 2][aRow] = av.z; As[aK4 + 3][aRow] = av.w;

        float4 bv = make_float4(0.f, 0.f, 0.f, 0.f);
        int gc = colBase + bC4;
        const float* brow = B + (size_t)(k0 + bK) * Nc;
        if (gc + 3 < Nc) bv = *reinterpret_cast<const float4*>(brow + gc);
        else {
            if (gc + 0 < Nc) bv.x = brow[gc + 0];
            if (gc + 1 < Nc) bv.y = brow[gc + 1];
            if (gc + 2 < Nc) bv.z = brow[gc + 2];
            if (gc + 3 < Nc) bv.w = brow[gc + 3];
        }
        *reinterpret_cast<float4*>(&Bs[bK][bC4]) = bv;
        __syncthreads();

        #pragma unroll
        for (int k = 0; k < BK; k++) {
            float4 a4 = *reinterpret_cast<const float4*>(&As[k][ty * 4]);
            float4 b4 = *reinterpret_cast<const float4*>(&Bs[k][tx * 4]);
            float a[4] = {a4.x, a4.y, a4.z, a4.w};
            float b[4] = {b4.x, b4.y, b4.z, b4.w};
            #pragma unroll
            for (int i = 0; i < 4; i++)
                #pragma unroll
                for (int j = 0; j < 4; j++)
                    acc[i][j] += a[i] * b[j];
        }
        __syncthreads();
    }

    #pragma unroll
    for (int i = 0; i < 4; i++) {
        int gr = rowBase + ty * 4 + i;
        if (gr >= M) continue;
        #pragma unroll
        for (int j = 0; j < 4; j++) {
            int gc = colBase + tx * 4 + j;
            if (gc < Nc) C[(size_t)gr * Nc + gc] = acc[i][j];
        }
    }
}

// ---------------- per-node attention coefficients ----------------------------
__global__ void k_attn(const float* __restrict__ att_src, const float* __restrict__ att_dst) {
    int gt = blockIdx.x * blockDim.x + threadIdx.x;
    int w = gt >> 5, lane = gt & 31;
    if (w >= NNODES) return;
    float4 hv = *reinterpret_cast<const float4*>(g_h + (size_t)w * HC + lane * 4);
    float4 as = *reinterpret_cast<const float4*>(att_src + lane * 4);
    float4 ad = *reinterpret_cast<const float4*>(att_dst + lane * 4);
    float ss = hv.x * as.x + hv.y * as.y + hv.z * as.z + hv.w * as.w;
    float sd = hv.x * ad.x + hv.y * ad.y + hv.z * ad.z + hv.w * ad.w;
    for (int o = 8; o; o >>= 1) {
        ss += __shfl_xor_sync(0xffffffffu, ss, o);
        sd += __shfl_xor_sync(0xffffffffu, sd, o);
    }
    if ((lane & 15) == 0) {
        int h = lane >> 4;
        g_asrc[w * 2 + h] = ss;
        g_adst[w * 2 + h] = sd;
    }
}

// ---------------- per-node segment softmax (gather, no atomics) --------------
__global__ void k_softmax() {
    int gt = blockIdx.x * blockDim.x + threadIdx.x;
    int w = gt >> 5, lane = gt & 31;
    if (w >= NNODES) return;
    int beg = g_rowptr[w], end = g_rowptr[w + 1];
    float ad0 = g_adst[w * 2], ad1 = g_adst[w * 2 + 1];
    float m0 = -3.0e38f, m1 = -3.0e38f;
    for (int p = beg + lane; p < end; p += 32) {
        int s = g_csr_src[p];
        float e0 = g_asrc[s * 2]     + ad0;
        float e1 = g_asrc[s * 2 + 1] + ad1;
        e0 = e0 > 0.f ? e0 : NEG_SLOPE * e0;
        e1 = e1 > 0.f ? e1 : NEG_SLOPE * e1;
        float2 ev; ev.x = e0; ev.y = e1;
        *reinterpret_cast<float2*>(g_e + 2 * p) = ev;
        m0 = fmaxf(m0, e0); m1 = fmaxf(m1, e1);
    }
    for (int o = 16; o; o >>= 1) {
        m0 = fmaxf(m0, __shfl_xor_sync(0xffffffffu, m0, o));
        m1 = fmaxf(m1, __shfl_xor_sync(0xffffffffu, m1, o));
    }
    float s0 = 0.f, s1 = 0.f;
    for (int p = beg + lane; p < end; p += 32) {
        float2 ev = *reinterpret_cast<float2*>(g_e + 2 * p);
        float ex0 = expf(ev.x - m0);
        float ex1 = expf(ev.y - m1);
        ev.x = ex0; ev.y = ex1;
        *reinterpret_cast<float2*>(g_e + 2 * p) = ev;
        s0 += ex0; s1 += ex1;
    }
    for (int o = 16; o; o >>= 1) {
        s0 += __shfl_xor_sync(0xffffffffu, s0, o);
        s1 += __shfl_xor_sync(0xffffffffu, s1, o);
    }
    if (lane == 0) {
        g_invden[w * 2]     = 1.f / (s0 + 1e-16f);
        g_invden[w * 2 + 1] = 1.f / (s1 + 1e-16f);
    }
}

// ---------------- weighted aggregate (gather) + fused epilogue ---------------
template <bool FIRST>
__global__ void k_agg(const float* __restrict__ bias,
                      const float* __restrict__ gamma, const float* __restrict__ beta,
                      const float* __restrict__ mean,  const float* __restrict__ var) {
    int gt = blockIdx.x * blockDim.x + threadIdx.x;
    int w = gt >> 5, lane = gt & 31;
    if (w >= NNODES) return;
    int beg = g_rowptr[w], end = g_rowptr[w + 1];
    float invh = (lane < 16) ? g_invden[w * 2] : g_invden[w * 2 + 1];
    float4 acc = make_float4(0.f, 0.f, 0.f, 0.f);
    for (int p = beg; p < end; p++) {
        int s = g_csr_src[p];                                   // broadcast
        float2 ev = *reinterpret_cast<const float2*>(g_e + 2 * p);
        float alpha = ((lane < 16) ? ev.x : ev.y) * invh;
        float4 v = *reinterpret_cast<const float4*>(g_h + (size_t)s * HC + lane * 4);
        acc.x += alpha * v.x; acc.y += alpha * v.y;
        acc.z += alpha * v.z; acc.w += alpha * v.w;
    }
    int j = lane * 4;
    float4 b = *reinterpret_cast<const float4*>(bias + j);
    float4 r = make_float4(acc.x + b.x, acc.y + b.y, acc.z + b.z, acc.w + b.w);
    if (FIRST) {
        float4 gm = *reinterpret_cast<const float4*>(gamma + j);
        float4 bt = *reinterpret_cast<const float4*>(beta + j);
        float4 mn = *reinterpret_cast<const float4*>(mean + j);
        float4 vr = *reinterpret_cast<const float4*>(var + j);
        r.x = (r.x - mn.x) * rsqrtf(vr.x + BN_EPS) * gm.x + bt.x;
        r.y = (r.y - mn.y) * rsqrtf(vr.y + BN_EPS) * gm.y + bt.y;
        r.z = (r.z - mn.z) * rsqrtf(vr.z + BN_EPS) * gm.z + bt.z;
        r.w = (r.w - mn.w) * rsqrtf(vr.w + BN_EPS) * gm.w + bt.w;
        r.x = r.x > 0.f ? r.x : expm1f(r.x);
        r.y = r.y > 0.f ? r.y : expm1f(r.y);
        r.z = r.z > 0.f ? r.z : expm1f(r.z);
        r.w = r.w > 0.f ? r.w : expm1f(r.w);
        *reinterpret_cast<float4*>(g_x1 + (size_t)w * HC + j) = r;
    } else {
        float4 p1 = *reinterpret_cast<const float4*>(g_x1 + (size_t)w * HC + j);
        r.x = fmaxf(r.x, p1.x); r.y = fmaxf(r.y, p1.y);
        r.z = fmaxf(r.z, p1.z); r.w = fmaxf(r.w, p1.w);        // JK 'max' fused
        *reinterpret_cast<float4*>(g_x2 + (size_t)w * HC + j) = r;
    }
}

// ---------------- bias + row log-softmax -------------------------------------
__global__ void k_lsm(const float* __restrict__ bf, float* __restrict__ out) {
    int gt = blockIdx.x * blockDim.x + threadIdx.x;
    int w = gt >> 5, lane = gt & 31;
    if (w >= NNODES) return;
    const float* row = g_logits + (size_t)w * NOUTC;
    float l0 = row[lane] + bf[lane];
    float l1 = (lane < 8) ? (row[32 + lane] + bf[32 + lane]) : -3.0e38f;
    float m = fmaxf(l0, l1);
    for (int o = 16; o; o >>= 1) m = fmaxf(m, __shfl_xor_sync(0xffffffffu, m, o));
    float s = expf(l0 - m) + ((lane < 8) ? expf(l1 - m) : 0.f);
    for (int o = 16; o; o >>= 1) s += __shfl_xor_sync(0xffffffffu, s, o);
    float lse = m + logf(s);
    out[(size_t)w * NOUTC + lane] = l0 - lse;
    if (lane < 8) out[(size_t)w * NOUTC + 32 + lane] = l1 - lse;
}

// ---------------- launch -----------------------------------------------------
extern "C" void kernel_launch(void* const* d_in, const int* in_sizes, int n_in,
                              void* d_out, int out_size) {
    const float* x     = (const float*)d_in[0];
    const void*  ei    = d_in[1];
    const float* W1    = (const float*)d_in[2];
    const float* as1   = (const float*)d_in[3];
    const float* ad1   = (const float*)d_in[4];
    const float* b1    = (const float*)d_in[5];
    const float* gamma = (const float*)d_in[6];
    const float* beta  = (const float*)d_in[7];
    const float* mean  = (const float*)d_in[8];
    const float* var   = (const float*)d_in[9];
    const float* W2    = (const float*)d_in[10];
    const float* as2   = (const float*)d_in[11];
    const float* ad2   = (const float*)d_in[12];
    const float* b2    = (const float*)d_in[13];
    const float* Wf    = (const float*)d_in[14];
    const float* bf    = (const float*)d_in[15];
    float* out = (float*)d_out;

    float *hP, *x1P, *x2P, *lgP;
    cudaGetSymbolAddress((void**)&hP,  g_h);
    cudaGetSymbolAddress((void**)&x1P, g_x1);
    cudaGetSymbolAddress((void**)&x2P, g_x2);
    cudaGetSymbolAddress((void**)&lgP, g_logits);

    const int WPN = (NNODES * 32 + 255) / 256;   // warp-per-node grids

    k_detect<<<1, 32>>>((const int*)ei);
    k_zero<<<(NNODES + 255) / 256, 256>>>();
    k_count<<<(ETOT + 255) / 256, 256>>>(ei);
    k_scan1<<<NSCANB, 1024>>>();
    k_scan2<<<1, 32>>>();
    k_scan3<<<(NNODES + 255) / 256, 256>>>();
    k_fill<<<(ETOT + 255) / 256, 256>>>(ei);

    dim3 gemmG((NNODES + 127) / 128);
    dim3 g40((NOUTC + BN - 1) / BN, (NNODES + BM - 1) / BM);

    // layer 1
    k_sgemm128<<<gemmG, 256>>>(x, W1, hP, NNODES);
    k_attn<<<WPN, 256>>>(as1, ad1);
    k_softmax<<<WPN, 256>>>();
    k_agg<true><<<WPN, 256>>>(b1, gamma, beta, mean, var);

    // layer 2
    k_sgemm128<<<gemmG, 256>>>(x1P, W2, hP, NNODES);
    k_attn<<<WPN, 256>>>(as2, ad2);
    k_softmax<<<WPN, 256>>>();
    k_agg<false><<<WPN, 256>>>(b2, nullptr, nullptr, nullptr, nullptr);

    // head
    k_sgemm<<<g40, 256>>>(x2P, Wf, lgP, NNODES, NOUTC, HC);
    k_lsm<<<WPN, 256>>>(bf, out);
}